// round 10
// baseline (speedup 1.0000x reference)
#include <cuda_runtime.h>
#include <cstdint>
#include <cstddef>

// ---- config -----------------------------------------------------------------
#define PARTITIONABLE 1     // modern JAX default (jax_threefry_partitionable=True)

#define NPTS   131072
#define DIM    256
#define KC     128
#define NCHUNK 512          // chunks of 256 points
#define NTILE  1024         // GEMM tiles of 128 points
#define NBLK   148          // persistent grid: one block per SM, co-resident
#define LLOYD_MAX 100
#define TINYF 1.1754943508222875e-38f
#define ASTR 132

// ---- persistent device state ------------------------------------------------
__device__ float    g_cents[KC * DIM];
__device__ float    g_newc[KC * DIM];
__device__ float    g_c2[KC];
__device__ float    g_x2[NPTS];
__device__ int      g_ids[NPTS];
__device__ float    g_mind[NPTS];
__device__ float    g_sumpart[NBLK];
__device__ float    g_amaxv[NBLK];
__device__ int      g_amaxi[NBLK];
__device__ unsigned g_keys[KC][2];
__device__ int      g_hist[NCHUNK * KC];
__device__ int      g_off[NCHUNK * KC];
__device__ int      g_base[KC];
__device__ int      g_tot[KC];
__device__ int      g_order[NPTS];
__device__ float    g_losspart[NTILE];
__device__ int      g_notclose;

// ---- software grid barrier (all NBLK blocks co-resident) --------------------
__device__ unsigned g_barcnt = 0;
__device__ volatile unsigned g_bargen = 0;

__device__ __forceinline__ void gbar() {
    __syncthreads();
    if (threadIdx.x == 0) {
        __threadfence();
        unsigned gen = g_bargen;
        if (atomicAdd(&g_barcnt, 1u) == NBLK - 1u) {
            g_barcnt = 0;
            __threadfence();
            g_bargen = gen + 1u;
        } else {
            while (g_bargen == gen) { __nanosleep(32); }
        }
        __threadfence();
    }
    __syncthreads();
}

// ---- packed f32x2 helpers (bit-exact: 2 independent IEEE rn fp32 FMAs) ------
__device__ __forceinline__ unsigned long long splat2(float v) {
    unsigned long long r;
    asm("mov.b64 %0, {%1, %1};" : "=l"(r) : "f"(v));
    return r;
}
__device__ __forceinline__ void ffma2(unsigned long long& d,
                                      unsigned long long a, unsigned long long b) {
    asm("fma.rn.f32x2 %0, %1, %2, %0;" : "+l"(d) : "l"(a), "l"(b));
}
__device__ __forceinline__ void unpack2(unsigned long long v, float& lo, float& hi) {
    asm("mov.b64 {%0, %1}, %2;" : "=f"(lo), "=f"(hi) : "l"(v));
}

// ---- JAX threefry2x32 (exact) ----------------------------------------------
__device__ __forceinline__ unsigned rotl32(unsigned v, int r) {
    return (v << r) | (v >> (32 - r));
}

__device__ __forceinline__ void threefry(unsigned k0, unsigned k1,
                                         unsigned c0, unsigned c1,
                                         unsigned& o0, unsigned& o1) {
    unsigned ks2 = k0 ^ k1 ^ 0x1BD11BDAu;
    unsigned x0 = c0 + k0, x1 = c1 + k1;
#define TFR(r) { x0 += x1; x1 = rotl32(x1, r); x1 ^= x0; }
    TFR(13) TFR(15) TFR(26) TFR(6)
    x0 += k1;  x1 += ks2 + 1u;
    TFR(17) TFR(29) TFR(16) TFR(24)
    x0 += ks2; x1 += k0 + 2u;
    TFR(13) TFR(15) TFR(26) TFR(6)
    x0 += k0;  x1 += k1 + 3u;
    TFR(17) TFR(29) TFR(16) TFR(24)
    x0 += k1;  x1 += ks2 + 4u;
    TFR(13) TFR(15) TFR(26) TFR(6)
    x0 += ks2; x1 += k0 + 5u;
#undef TFR
    o0 = x0; o1 = x1;
}

// =============================================================================
// Kernel 1: seed + x2 + full kmeans++ (persistent, software grid barriers)
// =============================================================================
__global__ __launch_bounds__(256) void k_init(const float* __restrict__ x) {
    __shared__ float sm[256 * 33];
    __shared__ float sc[32];
    __shared__ float sred[256];
    __shared__ int   sidx[256];
    __shared__ float s_S;
    __shared__ float s_bv;
    __shared__ int   s_bi;
    __shared__ int   s_idx;
    int tid = threadIdx.x;

    // ---- seed: split chain + randint (with its internal split) + center 0 ----
    if (blockIdx.x == 0) {
        if (tid == 0) {
            unsigned kh = 0u, kl = 42u;   // jax.random.key(42) -> (0, 42)
            for (int i = 0; i < KC; i++) {
#if PARTITIONABLE
                unsigned a0, a1, b0, b1;
                threefry(kh, kl, 0u, 0u, a0, a1);   // new key = enc(0,0)
                threefry(kh, kl, 0u, 1u, b0, b1);   // subkey  = enc(0,1)
                g_keys[i][0] = b0; g_keys[i][1] = b1;
                kh = a0; kl = a1;
#else
                unsigned p0, q0, p1, q1;
                threefry(kh, kl, 0u, 2u, p0, q0);
                threefry(kh, kl, 1u, 3u, p1, q1);
                g_keys[i][0] = q0; g_keys[i][1] = q1;
                kh = p0; kl = p1;
#endif
            }
            unsigned lo;
#if PARTITIONABLE
            unsigned k2h, k2l, a, b;
            threefry(g_keys[0][0], g_keys[0][1], 0u, 1u, k2h, k2l);
            threefry(k2h, k2l, 0u, 0u, a, b);
            lo = a ^ b;
#else
            unsigned p0, q0, p1, q1, a, b;
            threefry(g_keys[0][0], g_keys[0][1], 0u, 2u, p0, q0);
            threefry(g_keys[0][0], g_keys[0][1], 1u, 3u, p1, q1);
            threefry(q0, q1, 0u, 0u, a, b);
            lo = a;
#endif
            s_idx = (int)(lo & (NPTS - 1));
            g_notclose = 0;
        }
        __syncthreads();
        g_cents[tid] = x[(size_t)s_idx * DIM + tid];
    }
    gbar();

    // ---- fused pass: x2 (exact fold) + distance to center 0 ------------------
    {
        float bsum = 0.f;
        for (int ch0 = blockIdx.x; ch0 < NCHUNK; ch0 += NBLK) {
            int p0 = ch0 * 256;
            float accx = 0.f, accd = 0.f;
            for (int ch = 0; ch < 8; ch++) {
                if (tid < 32) sc[tid] = g_cents[ch * 32 + tid];
#pragma unroll
                for (int l = 0; l < 32; l++) {
                    int idx = l * 256 + tid;
                    int row = idx >> 5, col = idx & 31;
                    sm[row * 33 + col] = x[(size_t)(p0 + row) * DIM + ch * 32 + col];
                }
                __syncthreads();
#pragma unroll
                for (int col = 0; col < 32; col++) {
                    float v = sm[tid * 33 + col];
                    accx = __fadd_rn(accx, __fmul_rn(v, v));
                    float d = __fsub_rn(v, sc[col]);
                    accd = __fadd_rn(accd, __fmul_rn(d, d));
                }
                __syncthreads();
            }
            g_x2[p0 + tid] = accx;
            float dc = __fsqrt_rn(fmaxf(accd, 0.f));
            g_mind[p0 + tid] = dc;
            sred[tid] = dc;
            __syncthreads();
            for (int o = 128; o; o >>= 1) {
                if (tid < o) sred[tid] += sred[tid + o];
                __syncthreads();
            }
            if (tid == 0) bsum += sred[0];
            __syncthreads();
        }
        if (tid == 0) g_sumpart[blockIdx.x] = bsum;
    }
    gbar();

    // ---- kmeans++ loop --------------------------------------------------------
    for (int i = 1; i < KC; i++) {
        // sampling: S, per-point gumbel logits, per-block argmax partial
        if (tid == 0) {
            float S = 0.f;
            for (int b = 0; b < NBLK; b++) S += g_sumpart[b];
            s_S = S;
            s_bv = -3.4e38f; s_bi = 0x7fffffff;
        }
        __syncthreads();
        float S = s_S;
        unsigned kh = g_keys[i][0], kl = g_keys[i][1];
        for (int ch0 = blockIdx.x; ch0 < NCHUNK; ch0 += NBLK) {
            int p = ch0 * 256 + tid;
            unsigned bits;
#if PARTITIONABLE
            { unsigned a, b; threefry(kh, kl, 0u, (unsigned)p, a, b); bits = a ^ b; }
#else
            {
                unsigned a, b;
                if (p < NPTS / 2) { threefry(kh, kl, (unsigned)p, (unsigned)(p + NPTS / 2), a, b); bits = a; }
                else              { threefry(kh, kl, (unsigned)(p - NPTS / 2), (unsigned)p, a, b); bits = b; }
            }
#endif
            float f = __fsub_rn(__uint_as_float((bits >> 9) | 0x3f800000u), 1.0f);
            float u = fmaxf(__fadd_rn(f, TINYF), TINYF);
            float g = -logf(-logf(u));
            float val = __fadd_rn(logf(__fadd_rn(__fdiv_rn(g_mind[p], S), 1e-30f)), g);

            sred[tid] = val; sidx[tid] = p;
            __syncthreads();
            for (int o = 128; o; o >>= 1) {
                if (tid < o) {
                    float v2 = sred[tid + o]; int i2 = sidx[tid + o];
                    if (v2 > sred[tid] || (v2 == sred[tid] && i2 < sidx[tid])) {
                        sred[tid] = v2; sidx[tid] = i2;
                    }
                }
                __syncthreads();
            }
            if (tid == 0) {
                if (sred[0] > s_bv || (sred[0] == s_bv && sidx[0] < s_bi)) {
                    s_bv = sred[0]; s_bi = sidx[0];
                }
            }
            __syncthreads();
        }
        if (tid == 0) { g_amaxv[blockIdx.x] = s_bv; g_amaxi[blockIdx.x] = s_bi; }
        gbar();

        // pick winner, copy center i
        if (blockIdx.x == 0) {
            if (tid == 0) {
                float bv = g_amaxv[0]; int bi = g_amaxi[0];
                for (int b = 1; b < NBLK; b++) {
                    float v = g_amaxv[b]; int ii = g_amaxi[b];
                    if (v > bv || (v == bv && ii < bi)) { bv = v; bi = ii; }
                }
                s_idx = bi;
            }
            __syncthreads();
            g_cents[i * DIM + tid] = x[(size_t)s_idx * DIM + tid];
        }
        gbar();

        // min_d update vs center i (exact fold), partial sums
        if (i < KC - 1) {
            float bsum = 0.f;
            for (int ch0 = blockIdx.x; ch0 < NCHUNK; ch0 += NBLK) {
                int p0 = ch0 * 256;
                float accd = 0.f;
                for (int ch = 0; ch < 8; ch++) {
                    if (tid < 32) sc[tid] = g_cents[i * DIM + ch * 32 + tid];
#pragma unroll
                    for (int l = 0; l < 32; l++) {
                        int idx = l * 256 + tid;
                        int row = idx >> 5, col = idx & 31;
                        sm[row * 33 + col] = x[(size_t)(p0 + row) * DIM + ch * 32 + col];
                    }
                    __syncthreads();
#pragma unroll
                    for (int col = 0; col < 32; col++) {
                        float d = __fsub_rn(sm[tid * 33 + col], sc[col]);
                        accd = __fadd_rn(accd, __fmul_rn(d, d));
                    }
                    __syncthreads();
                }
                float dc = __fsqrt_rn(fmaxf(accd, 0.f));
                int p = p0 + tid;
                float m = fminf(g_mind[p], dc);
                g_mind[p] = m;
                sred[tid] = m;
                __syncthreads();
                for (int o = 128; o; o >>= 1) {
                    if (tid < o) sred[tid] += sred[tid + o];
                    __syncthreads();
                }
                if (tid == 0) bsum += sred[0];
                __syncthreads();
            }
            if (tid == 0) g_sumpart[blockIdx.x] = bsum;
            gbar();
        }
    }
}

// ---- shared GEMM tile body: f32x2-packed, per-output k-ascending FMA chain --
// Computes acc2[i2][j]: lanes (row 2*i2, row 2*i2+1) x col j, for the 128x128
// tile at p0. As/Bs are caller's smem. Bit-identical to the scalar version.
struct TileAcc { unsigned long long a2[4][8]; };

__device__ __forceinline__ void gemm_tile(const float* __restrict__ x,
                                          const float* __restrict__ cents,
                                          float* As, float* Bs,
                                          int p0, int tid, TileAcc& T) {
    int tx = tid & 15, ty = tid >> 4;
#pragma unroll
    for (int i = 0; i < 4; i++)
#pragma unroll
        for (int j = 0; j < 8; j++) T.a2[i][j] = 0ull;

    // prefetch stage 0
    float4 pa[4], pb[4];
#pragma unroll
    for (int l = 0; l < 4; l++) {
        int idx = tid + 256 * l;
        int pt = idx >> 3, j = idx & 7;
        pa[l] = *(const float4*)&x[(size_t)(p0 + pt) * DIM + j * 4];
        pb[l] = *(const float4*)&cents[pt * DIM + j * 4];
    }

    for (int k0 = 0; k0 < DIM; k0 += 32) {
#pragma unroll
        for (int l = 0; l < 4; l++) {
            int idx = tid + 256 * l;
            int pt = idx >> 3, j = idx & 7;
            As[(j * 4 + 0) * ASTR + pt] = pa[l].x; As[(j * 4 + 1) * ASTR + pt] = pa[l].y;
            As[(j * 4 + 2) * ASTR + pt] = pa[l].z; As[(j * 4 + 3) * ASTR + pt] = pa[l].w;
            Bs[(j * 4 + 0) * ASTR + pt] = pb[l].x; Bs[(j * 4 + 1) * ASTR + pt] = pb[l].y;
            Bs[(j * 4 + 2) * ASTR + pt] = pb[l].z; Bs[(j * 4 + 3) * ASTR + pt] = pb[l].w;
        }
        __syncthreads();
        if (k0 + 32 < DIM) {
            int kn = k0 + 32;
#pragma unroll
            for (int l = 0; l < 4; l++) {
                int idx = tid + 256 * l;
                int pt = idx >> 3, j = idx & 7;
                pa[l] = *(const float4*)&x[(size_t)(p0 + pt) * DIM + kn + j * 4];
                pb[l] = *(const float4*)&cents[pt * DIM + kn + j * 4];
            }
        }
#pragma unroll
        for (int kk = 0; kk < 32; kk++) {
            // a row-pairs come free as 16B-aligned packed loads (ASTR*4 = 33*16)
            ulonglong2 a01 = *(ulonglong2*)&As[kk * ASTR + ty * 8];
            ulonglong2 a23 = *(ulonglong2*)&As[kk * ASTR + ty * 8 + 4];
            unsigned long long ap[4] = {a01.x, a01.y, a23.x, a23.y};
            float4 b0 = *(float4*)&Bs[kk * ASTR + tx * 8];
            float4 b1 = *(float4*)&Bs[kk * ASTR + tx * 8 + 4];
            unsigned long long bs[8] = {
                splat2(b0.x), splat2(b0.y), splat2(b0.z), splat2(b0.w),
                splat2(b1.x), splat2(b1.y), splat2(b1.z), splat2(b1.w)
            };
#pragma unroll
            for (int i2 = 0; i2 < 4; i2++)
#pragma unroll
                for (int j = 0; j < 8; j++)
                    ffma2(T.a2[i2][j], ap[i2], bs[j]);
        }
        __syncthreads();
    }
}

// =============================================================================
// Kernel 2: full Lloyd loop (persistent), device-side convergence break
// =============================================================================
__global__ __launch_bounds__(256, 1) void k_lloyd(const float* __restrict__ x) {
    __shared__ __align__(16) float As[32 * ASTR];
    __shared__ __align__(16) float Bs[32 * ASTR];
    __shared__ int   sh[KC];
    __shared__ int   soffw[8][KC];
    __shared__ float smc[256];
    int tid = threadIdx.x;

    // c2 init (exact sequential fold)
    if (blockIdx.x < KC) {
        smc[tid] = g_cents[blockIdx.x * DIM + tid];
        __syncthreads();
        if (tid == 0) {
            float s = 0.f;
            for (int d = 0; d < DIM; d++)
                s = __fadd_rn(s, __fmul_rn(smc[d], smc[d]));
            g_c2[blockIdx.x] = s;
        }
    }
    gbar();

    for (int it = 0; it < LLOYD_MAX; it++) {
        // ---- assign: f32x2 tile GEMM + quantized comparator ----
        int tx = tid & 15, ty = tid >> 4;
        for (int t = blockIdx.x; t < NTILE; t += NBLK) {
            int p0 = t * 128;
            TileAcc T;
            gemm_tile(x, g_cents, As, Bs, p0, tid, T);
            // ref comparator: d = sqrt(max((x2+c2) - 2*dot, 0)); argmin, first index
#pragma unroll
            for (int i = 0; i < 8; i++) {
                float x2p = g_x2[p0 + ty * 8 + i];
                float bv = 3.4e38f; int bc = 0;
#pragma unroll
                for (int j = 0; j < 8; j++) {
                    int c = tx * 8 + j;
                    float lo, hi;
                    unpack2(T.a2[i >> 1][j], lo, hi);
                    float dot = (i & 1) ? hi : lo;
                    float d2 = __fsub_rn(__fadd_rn(x2p, g_c2[c]), __fmul_rn(2.0f, dot));
                    float d = __fsqrt_rn(fmaxf(d2, 0.0f));
                    if (d < bv) { bv = d; bc = c; }
                }
#pragma unroll
                for (int o = 8; o; o >>= 1) {
                    float ov = __shfl_xor_sync(0xffffffffu, bv, o, 16);
                    int   oc = __shfl_xor_sync(0xffffffffu, bc, o, 16);
                    if (ov < bv || (ov == bv && oc < bc)) { bv = ov; bc = oc; }
                }
                if (tx == 0) g_ids[p0 + ty * 8 + i] = bc;
            }
        }
        gbar();

        if (blockIdx.x == 0 && tid == 0) g_notclose = 0;

        // ---- per-chunk histograms ----
        for (int b = blockIdx.x; b < NCHUNK; b += NBLK) {
            if (tid < KC) sh[tid] = 0;
            __syncthreads();
            atomicAdd(&sh[g_ids[b * 256 + tid]], 1);
            __syncthreads();
            if (tid < KC) g_hist[b * KC + tid] = sh[tid];
            __syncthreads();
        }
        gbar();

        // ---- prefix (block 0) ----
        if (blockIdx.x == 0) {
            int c = tid;
            if (c < KC) {
                int run = 0;
#pragma unroll 8
                for (int b = 0; b < NCHUNK; b++) {
                    int h = g_hist[b * KC + c];
                    g_off[b * KC + c] = run;
                    run += h;
                }
                g_tot[c] = run;
            }
            __syncthreads();
            if (tid == 0) {
                int base = 0;
                for (int k = 0; k < KC; k++) { g_base[k] = base; base += g_tot[k]; }
            }
            __syncthreads();
            if (c < KC) {
                int bc = g_base[c];
#pragma unroll 8
                for (int b = 0; b < NCHUNK; b++) g_off[b * KC + c] += bc;
            }
        }
        gbar();

        // ---- stable placement (one warp per chunk) ----
        {
            int w = tid >> 5, lane = tid & 31;
            for (int b = blockIdx.x * 8 + w; b < NCHUNK; b += NBLK * 8) {
                for (int l = lane; l < KC; l += 32) soffw[w][l] = g_off[b * KC + l];
                __syncwarp();
                if (lane == 0) {
                    for (int q = 0; q < 256; q++) {
                        int p = b * 256 + q;
                        int c = g_ids[p];
                        g_order[soffw[w][c]++] = p;
                    }
                }
                __syncwarp();
            }
        }
        gbar();

        // ---- segment mean: exact ascending-p fold ----
        if (blockIdx.x < KC) {
            int c = blockIdx.x;
            int j0 = g_base[c], cnt = g_tot[c];
            float acc = 0.f;
            int full = cnt & ~7;
            for (int j = 0; j < full; j += 8) {
                int pp[8];
#pragma unroll
                for (int q = 0; q < 8; q++) pp[q] = g_order[j0 + j + q];
                float vv[8];
#pragma unroll
                for (int q = 0; q < 8; q++) vv[q] = x[(size_t)pp[q] * DIM + tid];
#pragma unroll
                for (int q = 0; q < 8; q++) acc = __fadd_rn(acc, vv[q]);
            }
            for (int j = full; j < cnt; j++)
                acc = __fadd_rn(acc, x[(size_t)g_order[j0 + j] * DIM + tid]);

            float nv = __fdiv_rn(acc, fmaxf((float)cnt, 1.0f));
            g_newc[c * DIM + tid] = nv;
            float ov = g_cents[c * DIM + tid];
            float thr = __fadd_rn(1e-8f, __fmul_rn(1e-4f, fabsf(nv)));
            int fail = fabsf(__fsub_rn(ov, nv)) > thr;
            if (__syncthreads_or(fail)) { if (tid == 0) atomicOr(&g_notclose, 1); }
        }
        gbar();

        // ---- commit or break ----
        int done = (*(volatile int*)&g_notclose) == 0;
        if (!done && blockIdx.x < KC) {
            float v = g_newc[blockIdx.x * DIM + tid];
            g_cents[blockIdx.x * DIM + tid] = v;
            smc[tid] = v;
            __syncthreads();
            if (tid == 0) {
                float s = 0.f;
                for (int d = 0; d < DIM; d++)
                    s = __fadd_rn(s, __fmul_rn(smc[d], smc[d]));
                g_c2[blockIdx.x] = s;
            }
        }
        gbar();
        if (done) break;
    }
}

// =============================================================================
// Kernel 3: loss GEMM (f32x2) + fused log-softmax
// =============================================================================
__global__ __launch_bounds__(256, 1) void k_loss(const float* __restrict__ x) {
    __shared__ __align__(16) float As[32 * ASTR];
    __shared__ __align__(16) float Bs[32 * ASTR];
    __shared__ float sl[16];
    int tid = threadIdx.x;
    int tx = tid & 15, ty = tid >> 4;
    int p0 = blockIdx.x * 128;

    TileAcc T;
    gemm_tile(x, g_cents, As, Bs, p0, tid, T);

    float lsum = 0.f;
#pragma unroll
    for (int i = 0; i < 8; i++) {
        int p = p0 + ty * 8 + i;
        int id = g_ids[p];
        float z[8];
        float zm = -3.4e38f;
#pragma unroll
        for (int j = 0; j < 8; j++) {
            float lo, hi;
            unpack2(T.a2[i >> 1][j], lo, hi);
            float dot = (i & 1) ? hi : lo;
            z[j] = __fdiv_rn(dot, 0.1f);
            zm = fmaxf(zm, z[j]);
        }
#pragma unroll
        for (int o = 8; o; o >>= 1) zm = fmaxf(zm, __shfl_xor_sync(0xffffffffu, zm, o, 16));
        float se = 0.f, zid = 0.f;
#pragma unroll
        for (int j = 0; j < 8; j++) {
            se += expf(__fsub_rn(z[j], zm));
            if (tx * 8 + j == id) zid = z[j];
        }
#pragma unroll
        for (int o = 8; o; o >>= 1) {
            se += __shfl_xor_sync(0xffffffffu, se, o, 16);
            zid += __shfl_xor_sync(0xffffffffu, zid, o, 16);
        }
        if (tx == 0) lsum += (zm + logf(se)) - zid;
    }
    if (tx == 0) sl[ty] = lsum;
    __syncthreads();
    if (tid == 0) {
        float t = 0.f;
#pragma unroll
        for (int w = 0; w < 16; w++) t += sl[w];
        g_losspart[blockIdx.x] = t;
    }
}

__global__ void k_loss_final(float* __restrict__ out) {
    __shared__ float sr[256];
    int t = threadIdx.x;
    float s = g_losspart[t] + g_losspart[t + 256] +
              g_losspart[t + 512] + g_losspart[t + 768];
    sr[t] = s;
    __syncthreads();
    for (int o = 128; o; o >>= 1) { if (t < o) sr[t] += sr[t + o]; __syncthreads(); }
    if (t == 0) out[0] = __fdiv_rn(sr[0], (float)NPTS);
}

// ---- launch: 4 graph nodes total --------------------------------------------
extern "C" void kernel_launch(void* const* d_in, const int* in_sizes, int n_in,
                              void* d_out, int out_size) {
    const float* x = (const float*)d_in[0];
    float* out = (float*)d_out;
    (void)in_sizes; (void)n_in; (void)out_size;

    k_init<<<NBLK, 256>>>(x);
    k_lloyd<<<NBLK, 256>>>(x);
    k_loss<<<NTILE, 256>>>(x);
    k_loss_final<<<1, 256>>>(out);
}

// round 11
// speedup vs baseline: 1.1685x; 1.1685x over previous
#include <cuda_runtime.h>
#include <cstdint>
#include <cstddef>

// ---- config -----------------------------------------------------------------
#define PARTITIONABLE 1     // modern JAX default (jax_threefry_partitionable=True)

#define NPTS   131072
#define DIM    256
#define KC     128
#define NCHUNK 512          // k_init chunks of 256 points
#define NCH    1024         // Lloyd chunks of 128 points (== GEMM tiles)
#define NTILE  1024         // GEMM tiles of 128 points
#define NBLK   148          // persistent grid: one block per SM, co-resident
#define LLOYD_MAX 100
#define TINYF 1.1754943508222875e-38f
#define ASTR 132

// ---- persistent device state ------------------------------------------------
__device__ float    g_cents[KC * DIM];
__device__ float    g_newc[KC * DIM];
__device__ float    g_c2[KC];
__device__ float    g_x2[NPTS];
__device__ int      g_ids[NPTS];
__device__ float    g_mind[NPTS];
__device__ float    g_sumpart[NBLK];
__device__ float    g_amaxv[NBLK];
__device__ int      g_amaxi[NBLK];
__device__ unsigned g_keys[KC][2];
__device__ int      g_hist[NCH * KC];
__device__ int      g_off[NCH * KC];
__device__ int      g_base[KC];
__device__ int      g_tot[KC];
__device__ int      g_order[NPTS];
__device__ float    g_losspart[NTILE];
__device__ int      g_notclose;

// ---- software grid barrier (all NBLK blocks co-resident) --------------------
__device__ unsigned g_barcnt = 0;
__device__ volatile unsigned g_bargen = 0;

__device__ __forceinline__ void gbar() {
    __syncthreads();
    if (threadIdx.x == 0) {
        __threadfence();
        unsigned gen = g_bargen;
        if (atomicAdd(&g_barcnt, 1u) == NBLK - 1u) {
            g_barcnt = 0;
            __threadfence();
            g_bargen = gen + 1u;
        } else {
            while (g_bargen == gen) { __nanosleep(32); }
        }
        __threadfence();
    }
    __syncthreads();
}

// ---- JAX threefry2x32 (exact) ----------------------------------------------
__device__ __forceinline__ unsigned rotl32(unsigned v, int r) {
    return (v << r) | (v >> (32 - r));
}

__device__ __forceinline__ void threefry(unsigned k0, unsigned k1,
                                         unsigned c0, unsigned c1,
                                         unsigned& o0, unsigned& o1) {
    unsigned ks2 = k0 ^ k1 ^ 0x1BD11BDAu;
    unsigned x0 = c0 + k0, x1 = c1 + k1;
#define TFR(r) { x0 += x1; x1 = rotl32(x1, r); x1 ^= x0; }
    TFR(13) TFR(15) TFR(26) TFR(6)
    x0 += k1;  x1 += ks2 + 1u;
    TFR(17) TFR(29) TFR(16) TFR(24)
    x0 += ks2; x1 += k0 + 2u;
    TFR(13) TFR(15) TFR(26) TFR(6)
    x0 += k0;  x1 += k1 + 3u;
    TFR(17) TFR(29) TFR(16) TFR(24)
    x0 += k1;  x1 += ks2 + 4u;
    TFR(13) TFR(15) TFR(26) TFR(6)
    x0 += ks2; x1 += k0 + 5u;
#undef TFR
    o0 = x0; o1 = x1;
}

// =============================================================================
// Kernel 1: seed + x2 + full kmeans++ (persistent, software grid barriers)
// (verbatim round 9)
// =============================================================================
__global__ __launch_bounds__(256) void k_init(const float* __restrict__ x) {
    __shared__ float sm[256 * 33];
    __shared__ float sc[32];
    __shared__ float sred[256];
    __shared__ int   sidx[256];
    __shared__ float s_S;
    __shared__ float s_bv;
    __shared__ int   s_bi;
    __shared__ int   s_idx;
    int tid = threadIdx.x;

    if (blockIdx.x == 0) {
        if (tid == 0) {
            unsigned kh = 0u, kl = 42u;   // jax.random.key(42) -> (0, 42)
            for (int i = 0; i < KC; i++) {
#if PARTITIONABLE
                unsigned a0, a1, b0, b1;
                threefry(kh, kl, 0u, 0u, a0, a1);   // new key = enc(0,0)
                threefry(kh, kl, 0u, 1u, b0, b1);   // subkey  = enc(0,1)
                g_keys[i][0] = b0; g_keys[i][1] = b1;
                kh = a0; kl = a1;
#else
                unsigned p0, q0, p1, q1;
                threefry(kh, kl, 0u, 2u, p0, q0);
                threefry(kh, kl, 1u, 3u, p1, q1);
                g_keys[i][0] = q0; g_keys[i][1] = q1;
                kh = p0; kl = p1;
#endif
            }
            unsigned lo;
#if PARTITIONABLE
            unsigned k2h, k2l, a, b;
            threefry(g_keys[0][0], g_keys[0][1], 0u, 1u, k2h, k2l);
            threefry(k2h, k2l, 0u, 0u, a, b);
            lo = a ^ b;
#else
            unsigned p0, q0, p1, q1, a, b;
            threefry(g_keys[0][0], g_keys[0][1], 0u, 2u, p0, q0);
            threefry(g_keys[0][0], g_keys[0][1], 1u, 3u, p1, q1);
            threefry(q0, q1, 0u, 0u, a, b);
            lo = a;
#endif
            s_idx = (int)(lo & (NPTS - 1));
            g_notclose = 0;
        }
        __syncthreads();
        g_cents[tid] = x[(size_t)s_idx * DIM + tid];
    }
    gbar();

    // ---- fused pass: x2 (exact fold) + distance to center 0 ------------------
    {
        float bsum = 0.f;
        for (int ch0 = blockIdx.x; ch0 < NCHUNK; ch0 += NBLK) {
            int p0 = ch0 * 256;
            float accx = 0.f, accd = 0.f;
            for (int ch = 0; ch < 8; ch++) {
                if (tid < 32) sc[tid] = g_cents[ch * 32 + tid];
#pragma unroll
                for (int l = 0; l < 32; l++) {
                    int idx = l * 256 + tid;
                    int row = idx >> 5, col = idx & 31;
                    sm[row * 33 + col] = x[(size_t)(p0 + row) * DIM + ch * 32 + col];
                }
                __syncthreads();
#pragma unroll
                for (int col = 0; col < 32; col++) {
                    float v = sm[tid * 33 + col];
                    accx = __fadd_rn(accx, __fmul_rn(v, v));
                    float d = __fsub_rn(v, sc[col]);
                    accd = __fadd_rn(accd, __fmul_rn(d, d));
                }
                __syncthreads();
            }
            g_x2[p0 + tid] = accx;
            float dc = __fsqrt_rn(fmaxf(accd, 0.f));
            g_mind[p0 + tid] = dc;
            sred[tid] = dc;
            __syncthreads();
            for (int o = 128; o; o >>= 1) {
                if (tid < o) sred[tid] += sred[tid + o];
                __syncthreads();
            }
            if (tid == 0) bsum += sred[0];
            __syncthreads();
        }
        if (tid == 0) g_sumpart[blockIdx.x] = bsum;
    }
    gbar();

    // ---- kmeans++ loop --------------------------------------------------------
    for (int i = 1; i < KC; i++) {
        if (tid == 0) {
            float S = 0.f;
            for (int b = 0; b < NBLK; b++) S += g_sumpart[b];
            s_S = S;
            s_bv = -3.4e38f; s_bi = 0x7fffffff;
        }
        __syncthreads();
        float S = s_S;
        unsigned kh = g_keys[i][0], kl = g_keys[i][1];
        for (int ch0 = blockIdx.x; ch0 < NCHUNK; ch0 += NBLK) {
            int p = ch0 * 256 + tid;
            unsigned bits;
#if PARTITIONABLE
            { unsigned a, b; threefry(kh, kl, 0u, (unsigned)p, a, b); bits = a ^ b; }
#else
            {
                unsigned a, b;
                if (p < NPTS / 2) { threefry(kh, kl, (unsigned)p, (unsigned)(p + NPTS / 2), a, b); bits = a; }
                else              { threefry(kh, kl, (unsigned)(p - NPTS / 2), (unsigned)p, a, b); bits = b; }
            }
#endif
            float f = __fsub_rn(__uint_as_float((bits >> 9) | 0x3f800000u), 1.0f);
            float u = fmaxf(__fadd_rn(f, TINYF), TINYF);
            float g = -logf(-logf(u));
            float val = __fadd_rn(logf(__fadd_rn(__fdiv_rn(g_mind[p], S), 1e-30f)), g);

            sred[tid] = val; sidx[tid] = p;
            __syncthreads();
            for (int o = 128; o; o >>= 1) {
                if (tid < o) {
                    float v2 = sred[tid + o]; int i2 = sidx[tid + o];
                    if (v2 > sred[tid] || (v2 == sred[tid] && i2 < sidx[tid])) {
                        sred[tid] = v2; sidx[tid] = i2;
                    }
                }
                __syncthreads();
            }
            if (tid == 0) {
                if (sred[0] > s_bv || (sred[0] == s_bv && sidx[0] < s_bi)) {
                    s_bv = sred[0]; s_bi = sidx[0];
                }
            }
            __syncthreads();
        }
        if (tid == 0) { g_amaxv[blockIdx.x] = s_bv; g_amaxi[blockIdx.x] = s_bi; }
        gbar();

        if (blockIdx.x == 0) {
            if (tid == 0) {
                float bv = g_amaxv[0]; int bi = g_amaxi[0];
                for (int b = 1; b < NBLK; b++) {
                    float v = g_amaxv[b]; int ii = g_amaxi[b];
                    if (v > bv || (v == bv && ii < bi)) { bv = v; bi = ii; }
                }
                s_idx = bi;
            }
            __syncthreads();
            g_cents[i * DIM + tid] = x[(size_t)s_idx * DIM + tid];
        }
        gbar();

        if (i < KC - 1) {
            float bsum = 0.f;
            for (int ch0 = blockIdx.x; ch0 < NCHUNK; ch0 += NBLK) {
                int p0 = ch0 * 256;
                float accd = 0.f;
                for (int ch = 0; ch < 8; ch++) {
                    if (tid < 32) sc[tid] = g_cents[i * DIM + ch * 32 + tid];
#pragma unroll
                    for (int l = 0; l < 32; l++) {
                        int idx = l * 256 + tid;
                        int row = idx >> 5, col = idx & 31;
                        sm[row * 33 + col] = x[(size_t)(p0 + row) * DIM + ch * 32 + col];
                    }
                    __syncthreads();
#pragma unroll
                    for (int col = 0; col < 32; col++) {
                        float d = __fsub_rn(sm[tid * 33 + col], sc[col]);
                        accd = __fadd_rn(accd, __fmul_rn(d, d));
                    }
                    __syncthreads();
                }
                float dc = __fsqrt_rn(fmaxf(accd, 0.f));
                int p = p0 + tid;
                float m = fminf(g_mind[p], dc);
                g_mind[p] = m;
                sred[tid] = m;
                __syncthreads();
                for (int o = 128; o; o >>= 1) {
                    if (tid < o) sred[tid] += sred[tid + o];
                    __syncthreads();
                }
                if (tid == 0) bsum += sred[0];
                __syncthreads();
            }
            if (tid == 0) g_sumpart[blockIdx.x] = bsum;
            gbar();
        }
    }
}

// =============================================================================
// Kernel 2: full Lloyd loop (persistent), device-side convergence break
// GEMM body reverted to round-9 scalar form (proven FFMA-roofline, bit-exact).
// Histogram fused into assign epilogue; chunks = 128-pt tiles (NCH).
// =============================================================================
__global__ __launch_bounds__(256) void k_lloyd(const float* __restrict__ x) {
    __shared__ float As[32 * ASTR];
    __shared__ float Bs[32 * ASTR];
    __shared__ int   sh[KC];
    __shared__ int   soffw[8][KC];
    __shared__ float smc[256];
    int tid = threadIdx.x;

    // c2 init (exact sequential fold)
    if (blockIdx.x < KC) {
        smc[tid] = g_cents[blockIdx.x * DIM + tid];
        __syncthreads();
        if (tid == 0) {
            float s = 0.f;
            for (int d = 0; d < DIM; d++)
                s = __fadd_rn(s, __fmul_rn(smc[d], smc[d]));
            g_c2[blockIdx.x] = s;
        }
    }
    gbar();

    for (int it = 0; it < LLOYD_MAX; it++) {
        if (blockIdx.x == 0 && tid == 0) g_notclose = 0;
        // ---- assign: scalar tile GEMM + quantized comparator + fused hist ----
        int tx = tid & 15, ty = tid >> 4;
        for (int t = blockIdx.x; t < NTILE; t += NBLK) {
            int p0 = t * 128;
            float acc[8][8];
#pragma unroll
            for (int i = 0; i < 8; i++)
#pragma unroll
                for (int j = 0; j < 8; j++) acc[i][j] = 0.f;

            for (int k0 = 0; k0 < DIM; k0 += 32) {
#pragma unroll
                for (int l = 0; l < 4; l++) {
                    int idx = tid + 256 * l;
                    int pt = idx >> 3, j = idx & 7;
                    float4 va = *(const float4*)&x[(size_t)(p0 + pt) * DIM + k0 + j * 4];
                    As[(j * 4 + 0) * ASTR + pt] = va.x; As[(j * 4 + 1) * ASTR + pt] = va.y;
                    As[(j * 4 + 2) * ASTR + pt] = va.z; As[(j * 4 + 3) * ASTR + pt] = va.w;
                    float4 vb = *(const float4*)&g_cents[pt * DIM + k0 + j * 4];
                    Bs[(j * 4 + 0) * ASTR + pt] = vb.x; Bs[(j * 4 + 1) * ASTR + pt] = vb.y;
                    Bs[(j * 4 + 2) * ASTR + pt] = vb.z; Bs[(j * 4 + 3) * ASTR + pt] = vb.w;
                }
                __syncthreads();
#pragma unroll
                for (int kk = 0; kk < 32; kk++) {
                    float4 a0 = *(float4*)&As[kk * ASTR + ty * 8];
                    float4 a1 = *(float4*)&As[kk * ASTR + ty * 8 + 4];
                    float4 b0 = *(float4*)&Bs[kk * ASTR + tx * 8];
                    float4 b1 = *(float4*)&Bs[kk * ASTR + tx * 8 + 4];
                    float a[8] = {a0.x, a0.y, a0.z, a0.w, a1.x, a1.y, a1.z, a1.w};
                    float bb[8] = {b0.x, b0.y, b0.z, b0.w, b1.x, b1.y, b1.z, b1.w};
#pragma unroll
                    for (int i = 0; i < 8; i++)
#pragma unroll
                        for (int j = 0; j < 8; j++)
                            acc[i][j] = fmaf(a[i], bb[j], acc[i][j]);
                }
                __syncthreads();
            }
            // per-tile histogram prep
            if (tid < KC) sh[tid] = 0;
            __syncthreads();
            // ref comparator: d = sqrt(max((x2+c2) - 2*dot, 0)); argmin, first index
#pragma unroll
            for (int i = 0; i < 8; i++) {
                float x2p = g_x2[p0 + ty * 8 + i];
                float bv = 3.4e38f; int bc = 0;
#pragma unroll
                for (int j = 0; j < 8; j++) {
                    int c = tx * 8 + j;
                    float d2 = __fsub_rn(__fadd_rn(x2p, g_c2[c]), __fmul_rn(2.0f, acc[i][j]));
                    float d = __fsqrt_rn(fmaxf(d2, 0.0f));
                    if (d < bv) { bv = d; bc = c; }
                }
#pragma unroll
                for (int o = 8; o; o >>= 1) {
                    float ov = __shfl_xor_sync(0xffffffffu, bv, o, 16);
                    int   oc = __shfl_xor_sync(0xffffffffu, bc, o, 16);
                    if (ov < bv || (ov == bv && oc < bc)) { bv = ov; bc = oc; }
                }
                if (tx == 0) {
                    g_ids[p0 + ty * 8 + i] = bc;
                    atomicAdd(&sh[bc], 1);
                }
            }
            __syncthreads();
            if (tid < KC) g_hist[t * KC + tid] = sh[tid];
            __syncthreads();
        }
        gbar();

        // ---- prefix over NCH=1024 chunks (block 0) ----
        if (blockIdx.x == 0) {
            int c = tid;
            if (c < KC) {
                int run = 0;
#pragma unroll 8
                for (int b = 0; b < NCH; b++) {
                    int h = g_hist[b * KC + c];
                    g_off[b * KC + c] = run;
                    run += h;
                }
                g_tot[c] = run;
            }
            __syncthreads();
            if (tid == 0) {
                int base = 0;
                for (int k = 0; k < KC; k++) { g_base[k] = base; base += g_tot[k]; }
            }
            __syncthreads();
            if (c < KC) {
                int bc = g_base[c];
#pragma unroll 8
                for (int b = 0; b < NCH; b++) g_off[b * KC + c] += bc;
            }
        }
        gbar();

        // ---- stable placement (one warp per 128-pt chunk) ----
        {
            int w = tid >> 5, lane = tid & 31;
            for (int b = blockIdx.x * 8 + w; b < NCH; b += NBLK * 8) {
                for (int l = lane; l < KC; l += 32) soffw[w][l] = g_off[b * KC + l];
                __syncwarp();
                if (lane == 0) {
                    for (int q = 0; q < 128; q++) {
                        int p = b * 128 + q;
                        int c = g_ids[p];
                        g_order[soffw[w][c]++] = p;
                    }
                }
                __syncwarp();
            }
        }
        gbar();

        // ---- segment mean: exact ascending-p fold, 16-way load batches ----
        if (blockIdx.x < KC) {
            int c = blockIdx.x;
            int j0 = g_base[c], cnt = g_tot[c];
            float acc = 0.f;
            int full = cnt & ~15;
            for (int j = 0; j < full; j += 16) {
                int pp[16];
#pragma unroll
                for (int q = 0; q < 16; q++) pp[q] = g_order[j0 + j + q];
                float vv[16];
#pragma unroll
                for (int q = 0; q < 16; q++) vv[q] = x[(size_t)pp[q] * DIM + tid];
#pragma unroll
                for (int q = 0; q < 16; q++) acc = __fadd_rn(acc, vv[q]);
            }
            for (int j = full; j < cnt; j++)
                acc = __fadd_rn(acc, x[(size_t)g_order[j0 + j] * DIM + tid]);

            float nv = __fdiv_rn(acc, fmaxf((float)cnt, 1.0f));
            g_newc[c * DIM + tid] = nv;
            float ov = g_cents[c * DIM + tid];
            float thr = __fadd_rn(1e-8f, __fmul_rn(1e-4f, fabsf(nv)));
            int fail = fabsf(__fsub_rn(ov, nv)) > thr;
            if (__syncthreads_or(fail)) { if (tid == 0) atomicOr(&g_notclose, 1); }
        }
        gbar();

        // ---- commit or break ----
        int done = (*(volatile int*)&g_notclose) == 0;
        if (!done && blockIdx.x < KC) {
            float v = g_newc[blockIdx.x * DIM + tid];
            g_cents[blockIdx.x * DIM + tid] = v;
            smc[tid] = v;
            __syncthreads();
            if (tid == 0) {
                float s = 0.f;
                for (int d = 0; d < DIM; d++)
                    s = __fadd_rn(s, __fmul_rn(smc[d], smc[d]));
                g_c2[blockIdx.x] = s;
            }
        }
        gbar();
        if (done) break;
    }
}

// =============================================================================
// Kernel 3: loss GEMM + fused log-softmax (verbatim round 9 scalar)
// =============================================================================
__global__ __launch_bounds__(256, 2) void k_loss(const float* __restrict__ x) {
    __shared__ float As[32 * ASTR];
    __shared__ float Bs[32 * ASTR];
    __shared__ float sl[16];
    int tid = threadIdx.x;
    int tx = tid & 15, ty = tid >> 4;
    int p0 = blockIdx.x * 128;
    float acc[8][8];
#pragma unroll
    for (int i = 0; i < 8; i++)
#pragma unroll
        for (int j = 0; j < 8; j++) acc[i][j] = 0.f;

    for (int k0 = 0; k0 < DIM; k0 += 32) {
#pragma unroll
        for (int l = 0; l < 4; l++) {
            int idx = tid + 256 * l;
            int pt = idx >> 3, j = idx & 7;
            float4 va = *(const float4*)&x[(size_t)(p0 + pt) * DIM + k0 + j * 4];
            As[(j * 4 + 0) * ASTR + pt] = va.x; As[(j * 4 + 1) * ASTR + pt] = va.y;
            As[(j * 4 + 2) * ASTR + pt] = va.z; As[(j * 4 + 3) * ASTR + pt] = va.w;
            float4 vb = *(const float4*)&g_cents[pt * DIM + k0 + j * 4];
            Bs[(j * 4 + 0) * ASTR + pt] = vb.x; Bs[(j * 4 + 1) * ASTR + pt] = vb.y;
            Bs[(j * 4 + 2) * ASTR + pt] = vb.z; Bs[(j * 4 + 3) * ASTR + pt] = vb.w;
        }
        __syncthreads();
#pragma unroll
        for (int kk = 0; kk < 32; kk++) {
            float4 a0 = *(float4*)&As[kk * ASTR + ty * 8];
            float4 a1 = *(float4*)&As[kk * ASTR + ty * 8 + 4];
            float4 b0 = *(float4*)&Bs[kk * ASTR + tx * 8];
            float4 b1 = *(float4*)&Bs[kk * ASTR + tx * 8 + 4];
            float a[8] = {a0.x, a0.y, a0.z, a0.w, a1.x, a1.y, a1.z, a1.w};
            float bb[8] = {b0.x, b0.y, b0.z, b0.w, b1.x, b1.y, b1.z, b1.w};
#pragma unroll
            for (int i = 0; i < 8; i++)
#pragma unroll
                for (int j = 0; j < 8; j++)
                    acc[i][j] = fmaf(a[i], bb[j], acc[i][j]);
        }
        __syncthreads();
    }

    float lsum = 0.f;
#pragma unroll
    for (int i = 0; i < 8; i++) {
        int p = p0 + ty * 8 + i;
        int id = g_ids[p];
        float z[8];
        float zm = -3.4e38f;
#pragma unroll
        for (int j = 0; j < 8; j++) {
            z[j] = __fdiv_rn(acc[i][j], 0.1f);
            zm = fmaxf(zm, z[j]);
        }
#pragma unroll
        for (int o = 8; o; o >>= 1) zm = fmaxf(zm, __shfl_xor_sync(0xffffffffu, zm, o, 16));
        float se = 0.f, zid = 0.f;
#pragma unroll
        for (int j = 0; j < 8; j++) {
            se += expf(__fsub_rn(z[j], zm));
            if (tx * 8 + j == id) zid = z[j];
        }
#pragma unroll
        for (int o = 8; o; o >>= 1) {
            se += __shfl_xor_sync(0xffffffffu, se, o, 16);
            zid += __shfl_xor_sync(0xffffffffu, zid, o, 16);
        }
        if (tx == 0) lsum += (zm + logf(se)) - zid;
    }
    if (tx == 0) sl[ty] = lsum;
    __syncthreads();
    if (tid == 0) {
        float t = 0.f;
#pragma unroll
        for (int w = 0; w < 16; w++) t += sl[w];
        g_losspart[blockIdx.x] = t;
    }
}

__global__ void k_loss_final(float* __restrict__ out) {
    __shared__ float sr[256];
    int t = threadIdx.x;
    float s = g_losspart[t] + g_losspart[t + 256] +
              g_losspart[t + 512] + g_losspart[t + 768];
    sr[t] = s;
    __syncthreads();
    for (int o = 128; o; o >>= 1) { if (t < o) sr[t] += sr[t + o]; __syncthreads(); }
    if (t == 0) out[0] = __fdiv_rn(sr[0], (float)NPTS);
}

// ---- launch: 4 graph nodes total --------------------------------------------
extern "C" void kernel_launch(void* const* d_in, const int* in_sizes, int n_in,
                              void* d_out, int out_size) {
    const float* x = (const float*)d_in[0];
    float* out = (float*)d_out;
    (void)in_sizes; (void)n_in; (void)out_size;

    k_init<<<NBLK, 256>>>(x);
    k_lloyd<<<NBLK, 256>>>(x);
    k_loss<<<NTILE, 256>>>(x);
    k_loss_final<<<1, 256>>>(out);
}

// round 14
// speedup vs baseline: 1.1721x; 1.0031x over previous
#include <cuda_runtime.h>
#include <cstdint>
#include <cstddef>

// ---- config -----------------------------------------------------------------
#define PARTITIONABLE 1     // modern JAX default (jax_threefry_partitionable=True)

#define NPTS   131072
#define DIM    256
#define KC     128
#define NCHUNK 512          // k_init chunks of 256 points
#define NCH    1024         // Lloyd chunks of 128 points (== GEMM tiles)
#define NTILE  1024         // GEMM tiles of 128 points
#define NBLK   148          // persistent grid: one block per SM, co-resident
#define LLOYD_MAX 100
#define TINYF 1.1754943508222875e-38f
#define ASTR 132

// ---- persistent device state ------------------------------------------------
__device__ float    g_cents[KC * DIM];
__device__ float    g_newc[KC * DIM];
__device__ float    g_c2[KC];
__device__ float    g_x2[NPTS];
__device__ int      g_ids[NPTS];
__device__ float    g_mind[NPTS];
__device__ float    g_sumpart[NBLK];
__device__ float    g_amaxv[NBLK];
__device__ int      g_amaxi[NBLK];
__device__ unsigned g_keys[KC][2];
__device__ int      g_hist[NCH * KC];
__device__ int      g_off[NCH * KC];
__device__ int      g_base[KC];
__device__ int      g_tot[KC];
__device__ int      g_order[NPTS];
__device__ float    g_losspart[NTILE];
__device__ int      g_notclose;

// ---- software grid barrier (all NBLK blocks co-resident) --------------------
__device__ unsigned g_barcnt = 0;
__device__ volatile unsigned g_bargen = 0;

__device__ __forceinline__ void gbar() {
    __syncthreads();
    if (threadIdx.x == 0) {
        __threadfence();
        unsigned gen = g_bargen;
        if (atomicAdd(&g_barcnt, 1u) == NBLK - 1u) {
            g_barcnt = 0;
            __threadfence();
            g_bargen = gen + 1u;
        } else {
            while (g_bargen == gen) { __nanosleep(32); }
        }
        __threadfence();
    }
    __syncthreads();
}

// ---- JAX threefry2x32 (exact) ----------------------------------------------
__device__ __forceinline__ unsigned rotl32(unsigned v, int r) {
    return (v << r) | (v >> (32 - r));
}

__device__ __forceinline__ void threefry(unsigned k0, unsigned k1,
                                         unsigned c0, unsigned c1,
                                         unsigned& o0, unsigned& o1) {
    unsigned ks2 = k0 ^ k1 ^ 0x1BD11BDAu;
    unsigned x0 = c0 + k0, x1 = c1 + k1;
#define TFR(r) { x0 += x1; x1 = rotl32(x1, r); x1 ^= x0; }
    TFR(13) TFR(15) TFR(26) TFR(6)
    x0 += k1;  x1 += ks2 + 1u;
    TFR(17) TFR(29) TFR(16) TFR(24)
    x0 += ks2; x1 += k0 + 2u;
    TFR(13) TFR(15) TFR(26) TFR(6)
    x0 += k0;  x1 += k1 + 3u;
    TFR(17) TFR(29) TFR(16) TFR(24)
    x0 += k1;  x1 += ks2 + 4u;
    TFR(13) TFR(15) TFR(26) TFR(6)
    x0 += ks2; x1 += k0 + 5u;
#undef TFR
    o0 = x0; o1 = x1;
}

// =============================================================================
// Kernel 1: seed + x2 + full kmeans++ (persistent) — verbatim round 9
// =============================================================================
__global__ __launch_bounds__(256) void k_init(const float* __restrict__ x) {
    __shared__ float sm[256 * 33];
    __shared__ float sc[32];
    __shared__ float sred[256];
    __shared__ int   sidx[256];
    __shared__ float s_S;
    __shared__ float s_bv;
    __shared__ int   s_bi;
    __shared__ int   s_idx;
    int tid = threadIdx.x;

    if (blockIdx.x == 0) {
        if (tid == 0) {
            unsigned kh = 0u, kl = 42u;   // jax.random.key(42) -> (0, 42)
            for (int i = 0; i < KC; i++) {
#if PARTITIONABLE
                unsigned a0, a1, b0, b1;
                threefry(kh, kl, 0u, 0u, a0, a1);   // new key = enc(0,0)
                threefry(kh, kl, 0u, 1u, b0, b1);   // subkey  = enc(0,1)
                g_keys[i][0] = b0; g_keys[i][1] = b1;
                kh = a0; kl = a1;
#else
                unsigned p0, q0, p1, q1;
                threefry(kh, kl, 0u, 2u, p0, q0);
                threefry(kh, kl, 1u, 3u, p1, q1);
                g_keys[i][0] = q0; g_keys[i][1] = q1;
                kh = p0; kl = p1;
#endif
            }
            unsigned lo;
#if PARTITIONABLE
            unsigned k2h, k2l, a, b;
            threefry(g_keys[0][0], g_keys[0][1], 0u, 1u, k2h, k2l);
            threefry(k2h, k2l, 0u, 0u, a, b);
            lo = a ^ b;
#else
            unsigned p0, q0, p1, q1, a, b;
            threefry(g_keys[0][0], g_keys[0][1], 0u, 2u, p0, q0);
            threefry(g_keys[0][0], g_keys[0][1], 1u, 3u, p1, q1);
            threefry(q0, q1, 0u, 0u, a, b);
            lo = a;
#endif
            s_idx = (int)(lo & (NPTS - 1));
            g_notclose = 0;
        }
        __syncthreads();
        g_cents[tid] = x[(size_t)s_idx * DIM + tid];
    }
    gbar();

    // ---- fused pass: x2 (exact fold) + distance to center 0 ------------------
    {
        float bsum = 0.f;
        for (int ch0 = blockIdx.x; ch0 < NCHUNK; ch0 += NBLK) {
            int p0 = ch0 * 256;
            float accx = 0.f, accd = 0.f;
            for (int ch = 0; ch < 8; ch++) {
                if (tid < 32) sc[tid] = g_cents[ch * 32 + tid];
#pragma unroll
                for (int l = 0; l < 32; l++) {
                    int idx = l * 256 + tid;
                    int row = idx >> 5, col = idx & 31;
                    sm[row * 33 + col] = x[(size_t)(p0 + row) * DIM + ch * 32 + col];
                }
                __syncthreads();
#pragma unroll
                for (int col = 0; col < 32; col++) {
                    float v = sm[tid * 33 + col];
                    accx = __fadd_rn(accx, __fmul_rn(v, v));
                    float d = __fsub_rn(v, sc[col]);
                    accd = __fadd_rn(accd, __fmul_rn(d, d));
                }
                __syncthreads();
            }
            g_x2[p0 + tid] = accx;
            float dc = __fsqrt_rn(fmaxf(accd, 0.f));
            g_mind[p0 + tid] = dc;
            sred[tid] = dc;
            __syncthreads();
            for (int o = 128; o; o >>= 1) {
                if (tid < o) sred[tid] += sred[tid + o];
                __syncthreads();
            }
            if (tid == 0) bsum += sred[0];
            __syncthreads();
        }
        if (tid == 0) g_sumpart[blockIdx.x] = bsum;
    }
    gbar();

    // ---- kmeans++ loop --------------------------------------------------------
    for (int i = 1; i < KC; i++) {
        if (tid == 0) {
            float S = 0.f;
            for (int b = 0; b < NBLK; b++) S += g_sumpart[b];
            s_S = S;
            s_bv = -3.4e38f; s_bi = 0x7fffffff;
        }
        __syncthreads();
        float S = s_S;
        unsigned kh = g_keys[i][0], kl = g_keys[i][1];
        for (int ch0 = blockIdx.x; ch0 < NCHUNK; ch0 += NBLK) {
            int p = ch0 * 256 + tid;
            unsigned bits;
#if PARTITIONABLE
            { unsigned a, b; threefry(kh, kl, 0u, (unsigned)p, a, b); bits = a ^ b; }
#else
            {
                unsigned a, b;
                if (p < NPTS / 2) { threefry(kh, kl, (unsigned)p, (unsigned)(p + NPTS / 2), a, b); bits = a; }
                else              { threefry(kh, kl, (unsigned)(p - NPTS / 2), (unsigned)p, a, b); bits = b; }
            }
#endif
            float f = __fsub_rn(__uint_as_float((bits >> 9) | 0x3f800000u), 1.0f);
            float u = fmaxf(__fadd_rn(f, TINYF), TINYF);
            float g = -logf(-logf(u));
            float val = __fadd_rn(logf(__fadd_rn(__fdiv_rn(g_mind[p], S), 1e-30f)), g);

            sred[tid] = val; sidx[tid] = p;
            __syncthreads();
            for (int o = 128; o; o >>= 1) {
                if (tid < o) {
                    float v2 = sred[tid + o]; int i2 = sidx[tid + o];
                    if (v2 > sred[tid] || (v2 == sred[tid] && i2 < sidx[tid])) {
                        sred[tid] = v2; sidx[tid] = i2;
                    }
                }
                __syncthreads();
            }
            if (tid == 0) {
                if (sred[0] > s_bv || (sred[0] == s_bv && sidx[0] < s_bi)) {
                    s_bv = sred[0]; s_bi = sidx[0];
                }
            }
            __syncthreads();
        }
        if (tid == 0) { g_amaxv[blockIdx.x] = s_bv; g_amaxi[blockIdx.x] = s_bi; }
        gbar();

        if (blockIdx.x == 0) {
            if (tid == 0) {
                float bv = g_amaxv[0]; int bi = g_amaxi[0];
                for (int b = 1; b < NBLK; b++) {
                    float v = g_amaxv[b]; int ii = g_amaxi[b];
                    if (v > bv || (v == bv && ii < bi)) { bv = v; bi = ii; }
                }
                s_idx = bi;
            }
            __syncthreads();
            g_cents[i * DIM + tid] = x[(size_t)s_idx * DIM + tid];
        }
        gbar();

        if (i < KC - 1) {
            float bsum = 0.f;
            for (int ch0 = blockIdx.x; ch0 < NCHUNK; ch0 += NBLK) {
                int p0 = ch0 * 256;
                float accd = 0.f;
                for (int ch = 0; ch < 8; ch++) {
                    if (tid < 32) sc[tid] = g_cents[i * DIM + ch * 32 + tid];
#pragma unroll
                    for (int l = 0; l < 32; l++) {
                        int idx = l * 256 + tid;
                        int row = idx >> 5, col = idx & 31;
                        sm[row * 33 + col] = x[(size_t)(p0 + row) * DIM + ch * 32 + col];
                    }
                    __syncthreads();
#pragma unroll
                    for (int col = 0; col < 32; col++) {
                        float d = __fsub_rn(sm[tid * 33 + col], sc[col]);
                        accd = __fadd_rn(accd, __fmul_rn(d, d));
                    }
                    __syncthreads();
                }
                float dc = __fsqrt_rn(fmaxf(accd, 0.f));
                int p = p0 + tid;
                float m = fminf(g_mind[p], dc);
                g_mind[p] = m;
                sred[tid] = m;
                __syncthreads();
                for (int o = 128; o; o >>= 1) {
                    if (tid < o) sred[tid] += sred[tid + o];
                    __syncthreads();
                }
                if (tid == 0) bsum += sred[0];
                __syncthreads();
            }
            if (tid == 0) g_sumpart[blockIdx.x] = bsum;
            gbar();
        }
    }
}

// =============================================================================
// Kernel 2: Lloyd loop. GEMM + segmean verbatim round 9 (proven). Histogram
// fused into assign epilogue; prefix/placement at 128-pt tile granularity.
// =============================================================================
__global__ __launch_bounds__(256) void k_lloyd(const float* __restrict__ x) {
    __shared__ float As[32 * ASTR];
    __shared__ float Bs[32 * ASTR];
    __shared__ int   sh[KC];
    __shared__ int   soffw[8][KC];
    __shared__ float smc[256];
    int tid = threadIdx.x;

    // c2 init (exact sequential fold)
    if (blockIdx.x < KC) {
        smc[tid] = g_cents[blockIdx.x * DIM + tid];
        __syncthreads();
        if (tid == 0) {
            float s = 0.f;
            for (int d = 0; d < DIM; d++)
                s = __fadd_rn(s, __fmul_rn(smc[d], smc[d]));
            g_c2[blockIdx.x] = s;
        }
    }
    gbar();

    for (int it = 0; it < LLOYD_MAX; it++) {
        // ---- assign: round-9 scalar tile GEMM + comparator + fused hist ----
        int tx = tid & 15, ty = tid >> 4;
        for (int t = blockIdx.x; t < NTILE; t += NBLK) {
            int p0 = t * 128;
            float acc[8][8];
#pragma unroll
            for (int i = 0; i < 8; i++)
#pragma unroll
                for (int j = 0; j < 8; j++) acc[i][j] = 0.f;

            for (int k0 = 0; k0 < DIM; k0 += 32) {
#pragma unroll
                for (int l = 0; l < 4; l++) {
                    int idx = tid + 256 * l;
                    int pt = idx >> 3, j = idx & 7;
                    float4 va = *(const float4*)&x[(size_t)(p0 + pt) * DIM + k0 + j * 4];
                    As[(j * 4 + 0) * ASTR + pt] = va.x; As[(j * 4 + 1) * ASTR + pt] = va.y;
                    As[(j * 4 + 2) * ASTR + pt] = va.z; As[(j * 4 + 3) * ASTR + pt] = va.w;
                    float4 vb = *(const float4*)&g_cents[pt * DIM + k0 + j * 4];
                    Bs[(j * 4 + 0) * ASTR + pt] = vb.x; Bs[(j * 4 + 1) * ASTR + pt] = vb.y;
                    Bs[(j * 4 + 2) * ASTR + pt] = vb.z; Bs[(j * 4 + 3) * ASTR + pt] = vb.w;
                }
                __syncthreads();
#pragma unroll
                for (int kk = 0; kk < 32; kk++) {
                    float4 a0 = *(float4*)&As[kk * ASTR + ty * 8];
                    float4 a1 = *(float4*)&As[kk * ASTR + ty * 8 + 4];
                    float4 b0 = *(float4*)&Bs[kk * ASTR + tx * 8];
                    float4 b1 = *(float4*)&Bs[kk * ASTR + tx * 8 + 4];
                    float a[8] = {a0.x, a0.y, a0.z, a0.w, a1.x, a1.y, a1.z, a1.w};
                    float bb[8] = {b0.x, b0.y, b0.z, b0.w, b1.x, b1.y, b1.z, b1.w};
#pragma unroll
                    for (int i = 0; i < 8; i++)
#pragma unroll
                        for (int j = 0; j < 8; j++)
                            acc[i][j] = fmaf(a[i], bb[j], acc[i][j]);
                }
                __syncthreads();
            }
            // fused per-tile histogram
            if (tid < KC) sh[tid] = 0;
            __syncthreads();
            // ref comparator: d = sqrt(max((x2+c2) - 2*dot, 0)); argmin, first index
#pragma unroll
            for (int i = 0; i < 8; i++) {
                float x2p = g_x2[p0 + ty * 8 + i];
                float bv = 3.4e38f; int bc = 0;
#pragma unroll
                for (int j = 0; j < 8; j++) {
                    int c = tx * 8 + j;
                    float d2 = __fsub_rn(__fadd_rn(x2p, g_c2[c]), __fmul_rn(2.0f, acc[i][j]));
                    float d = __fsqrt_rn(fmaxf(d2, 0.0f));
                    if (d < bv) { bv = d; bc = c; }
                }
#pragma unroll
                for (int o = 8; o; o >>= 1) {
                    float ov = __shfl_xor_sync(0xffffffffu, bv, o, 16);
                    int   oc = __shfl_xor_sync(0xffffffffu, bc, o, 16);
                    if (ov < bv || (ov == bv && oc < bc)) { bv = ov; bc = oc; }
                }
                if (tx == 0) {
                    g_ids[p0 + ty * 8 + i] = bc;
                    atomicAdd(&sh[bc], 1);
                }
            }
            __syncthreads();
            if (tid < KC) g_hist[t * KC + tid] = sh[tid];
        }
        gbar();

        if (blockIdx.x == 0 && tid == 0) g_notclose = 0;

        // ---- prefix over NCH=1024 tiles (block 0) ----
        if (blockIdx.x == 0) {
            int c = tid;
            if (c < KC) {
                int run = 0;
#pragma unroll 8
                for (int b = 0; b < NCH; b++) {
                    int h = g_hist[b * KC + c];
                    g_off[b * KC + c] = run;
                    run += h;
                }
                g_tot[c] = run;
            }
            __syncthreads();
            if (tid == 0) {
                int base = 0;
                for (int k = 0; k < KC; k++) { g_base[k] = base; base += g_tot[k]; }
            }
            __syncthreads();
            if (c < KC) {
                int bc = g_base[c];
#pragma unroll 8
                for (int b = 0; b < NCH; b++) g_off[b * KC + c] += bc;
            }
        }
        gbar();

        // ---- stable placement (one warp per 128-pt tile) ----
        {
            int w = tid >> 5, lane = tid & 31;
            for (int b = blockIdx.x * 8 + w; b < NCH; b += NBLK * 8) {
                for (int l = lane; l < KC; l += 32) soffw[w][l] = g_off[b * KC + l];
                __syncwarp();
                if (lane == 0) {
                    for (int q = 0; q < 128; q++) {
                        int p = b * 128 + q;
                        int c = g_ids[p];
                        g_order[soffw[w][c]++] = p;
                    }
                }
                __syncwarp();
            }
        }
        gbar();

        // ---- segment mean: exact ascending-p fold, 8-way (verbatim round 9) ----
        if (blockIdx.x < KC) {
            int c = blockIdx.x;
            int j0 = g_base[c], cnt = g_tot[c];
            float acc = 0.f;
            int full = cnt & ~7;
            for (int j = 0; j < full; j += 8) {
                int pp[8];
#pragma unroll
                for (int q = 0; q < 8; q++) pp[q] = g_order[j0 + j + q];
                float vv[8];
#pragma unroll
                for (int q = 0; q < 8; q++) vv[q] = x[(size_t)pp[q] * DIM + tid];
#pragma unroll
                for (int q = 0; q < 8; q++) acc = __fadd_rn(acc, vv[q]);
            }
            for (int j = full; j < cnt; j++)
                acc = __fadd_rn(acc, x[(size_t)g_order[j0 + j] * DIM + tid]);

            float nv = __fdiv_rn(acc, fmaxf((float)cnt, 1.0f));
            g_newc[c * DIM + tid] = nv;
            float ov = g_cents[c * DIM + tid];
            float thr = __fadd_rn(1e-8f, __fmul_rn(1e-4f, fabsf(nv)));
            int fail = fabsf(__fsub_rn(ov, nv)) > thr;
            if (__syncthreads_or(fail)) { if (tid == 0) atomicOr(&g_notclose, 1); }
        }
        gbar();

        // ---- commit or break ----
        int done = (*(volatile int*)&g_notclose) == 0;
        if (!done && blockIdx.x < KC) {
            float v = g_newc[blockIdx.x * DIM + tid];
            g_cents[blockIdx.x * DIM + tid] = v;
            smc[tid] = v;
            __syncthreads();
            if (tid == 0) {
                float s = 0.f;
                for (int d = 0; d < DIM; d++)
                    s = __fadd_rn(s, __fmul_rn(smc[d], smc[d]));
                g_c2[blockIdx.x] = s;
            }
        }
        gbar();
        if (done) break;
    }
}

// =============================================================================
// Kernel 3: loss GEMM + fused log-softmax (verbatim round 9)
// =============================================================================
__global__ __launch_bounds__(256, 2) void k_loss(const float* __restrict__ x) {
    __shared__ float As[32 * ASTR];
    __shared__ float Bs[32 * ASTR];
    __shared__ float sl[16];
    int tid = threadIdx.x;
    int tx = tid & 15, ty = tid >> 4;
    int p0 = blockIdx.x * 128;
    float acc[8][8];
#pragma unroll
    for (int i = 0; i < 8; i++)
#pragma unroll
        for (int j = 0; j < 8; j++) acc[i][j] = 0.f;

    for (int k0 = 0; k0 < DIM; k0 += 32) {
#pragma unroll
        for (int l = 0; l < 4; l++) {
            int idx = tid + 256 * l;
            int pt = idx >> 3, j = idx & 7;
            float4 va = *(const float4*)&x[(size_t)(p0 + pt) * DIM + k0 + j * 4];
            As[(j * 4 + 0) * ASTR + pt] = va.x; As[(j * 4 + 1) * ASTR + pt] = va.y;
            As[(j * 4 + 2) * ASTR + pt] = va.z; As[(j * 4 + 3) * ASTR + pt] = va.w;
            float4 vb = *(const float4*)&g_cents[pt * DIM + k0 + j * 4];
            Bs[(j * 4 + 0) * ASTR + pt] = vb.x; Bs[(j * 4 + 1) * ASTR + pt] = vb.y;
            Bs[(j * 4 + 2) * ASTR + pt] = vb.z; Bs[(j * 4 + 3) * ASTR + pt] = vb.w;
        }
        __syncthreads();
#pragma unroll
        for (int kk = 0; kk < 32; kk++) {
            float4 a0 = *(float4*)&As[kk * ASTR + ty * 8];
            float4 a1 = *(float4*)&As[kk * ASTR + ty * 8 + 4];
            float4 b0 = *(float4*)&Bs[kk * ASTR + tx * 8];
            float4 b1 = *(float4*)&Bs[kk * ASTR + tx * 8 + 4];
            float a[8] = {a0.x, a0.y, a0.z, a0.w, a1.x, a1.y, a1.z, a1.w};
            float bb[8] = {b0.x, b0.y, b0.z, b0.w, b1.x, b1.y, b1.z, b1.w};
#pragma unroll
            for (int i = 0; i < 8; i++)
#pragma unroll
                for (int j = 0; j < 8; j++)
                    acc[i][j] = fmaf(a[i], bb[j], acc[i][j]);
        }
        __syncthreads();
    }

    float lsum = 0.f;
#pragma unroll
    for (int i = 0; i < 8; i++) {
        int p = p0 + ty * 8 + i;
        int id = g_ids[p];
        float z[8];
        float zm = -3.4e38f;
#pragma unroll
        for (int j = 0; j < 8; j++) {
            z[j] = __fdiv_rn(acc[i][j], 0.1f);
            zm = fmaxf(zm, z[j]);
        }
#pragma unroll
        for (int o = 8; o; o >>= 1) zm = fmaxf(zm, __shfl_xor_sync(0xffffffffu, zm, o, 16));
        float se = 0.f, zid = 0.f;
#pragma unroll
        for (int j = 0; j < 8; j++) {
            se += expf(__fsub_rn(z[j], zm));
            if (tx * 8 + j == id) zid = z[j];
        }
#pragma unroll
        for (int o = 8; o; o >>= 1) {
            se += __shfl_xor_sync(0xffffffffu, se, o, 16);
            zid += __shfl_xor_sync(0xffffffffu, zid, o, 16);
        }
        if (tx == 0) lsum += (zm + logf(se)) - zid;
    }
    if (tx == 0) sl[ty] = lsum;
    __syncthreads();
    if (tid == 0) {
        float t = 0.f;
#pragma unroll
        for (int w = 0; w < 16; w++) t += sl[w];
        g_losspart[blockIdx.x] = t;
    }
}

__global__ void k_loss_final(float* __restrict__ out) {
    __shared__ float sr[256];
    int t = threadIdx.x;
    float s = g_losspart[t] + g_losspart[t + 256] +
              g_losspart[t + 512] + g_losspart[t + 768];
    sr[t] = s;
    __syncthreads();
    for (int o = 128; o; o >>= 1) { if (t < o) sr[t] += sr[t + o]; __syncthreads(); }
    if (t == 0) out[0] = __fdiv_rn(sr[0], (float)NPTS);
}

// ---- launch: 4 graph nodes total --------------------------------------------
extern "C" void kernel_launch(void* const* d_in, const int* in_sizes, int n_in,
                              void* d_out, int out_size) {
    const float* x = (const float*)d_in[0];
    float* out = (float*)d_out;
    (void)in_sizes; (void)n_in; (void)out_size;

    k_init<<<NBLK, 256>>>(x);
    k_lloyd<<<NBLK, 256>>>(x);
    k_loss<<<NTILE, 256>>>(x);
    k_loss_final<<<1, 256>>>(out);
}

// round 15
// speedup vs baseline: 1.5240x; 1.3002x over previous
#include <cuda_runtime.h>
#include <cstdint>
#include <cstddef>

// ---- config -----------------------------------------------------------------
#define PARTITIONABLE 1     // modern JAX default (jax_threefry_partitionable=True)

#define NPTS   131072
#define DIM    256
#define KC     128
#define NCHUNK 512          // chunks of 256 points (init + lloyd hist/placement)
#define NTILE  1024         // GEMM tiles of 128 points
#define NBLK   148          // persistent grid: one block per SM, co-resident
#define LLOYD_MAX 100
#define TINYF 1.1754943508222875e-38f
#define ASTR 132

// ---- persistent device state ------------------------------------------------
__device__ float    g_cents[KC * DIM];
__device__ float    g_newc[KC * DIM];
__device__ float    g_c2[KC];
__device__ float    g_x2[NPTS];
__device__ int      g_ids[NPTS];
__device__ float    g_mind[NPTS];
__device__ float    g_sumpart[NBLK];
__device__ float    g_amaxv[NBLK];
__device__ int      g_amaxi[NBLK];
__device__ unsigned g_keys[KC][2];
__device__ int      g_hist[NCHUNK * KC];
__device__ int      g_off[NCHUNK * KC];
__device__ int      g_base[KC];
__device__ int      g_tot[KC];
__device__ int      g_order[NPTS];
__device__ float    g_losspart[NTILE];
__device__ int      g_notclose;

// ---- software grid barrier (all NBLK blocks co-resident) --------------------
__device__ unsigned g_barcnt = 0;
__device__ volatile unsigned g_bargen = 0;

__device__ __forceinline__ void gbar() {
    __syncthreads();
    if (threadIdx.x == 0) {
        __threadfence();
        unsigned gen = g_bargen;
        if (atomicAdd(&g_barcnt, 1u) == NBLK - 1u) {
            g_barcnt = 0;
            __threadfence();
            g_bargen = gen + 1u;
        } else {
            while (g_bargen == gen) { __nanosleep(32); }
        }
        __threadfence();
    }
    __syncthreads();
}

// ---- JAX threefry2x32 (exact) ----------------------------------------------
__device__ __forceinline__ unsigned rotl32(unsigned v, int r) {
    return (v << r) | (v >> (32 - r));
}

__device__ __forceinline__ void threefry(unsigned k0, unsigned k1,
                                         unsigned c0, unsigned c1,
                                         unsigned& o0, unsigned& o1) {
    unsigned ks2 = k0 ^ k1 ^ 0x1BD11BDAu;
    unsigned x0 = c0 + k0, x1 = c1 + k1;
#define TFR(r) { x0 += x1; x1 = rotl32(x1, r); x1 ^= x0; }
    TFR(13) TFR(15) TFR(26) TFR(6)
    x0 += k1;  x1 += ks2 + 1u;
    TFR(17) TFR(29) TFR(16) TFR(24)
    x0 += ks2; x1 += k0 + 2u;
    TFR(13) TFR(15) TFR(26) TFR(6)
    x0 += k0;  x1 += k1 + 3u;
    TFR(17) TFR(29) TFR(16) TFR(24)
    x0 += k1;  x1 += ks2 + 4u;
    TFR(13) TFR(15) TFR(26) TFR(6)
    x0 += ks2; x1 += k0 + 5u;
#undef TFR
    o0 = x0; o1 = x1;
}

// =============================================================================
// Kernel 1: seed + x2 + full kmeans++ (persistent) — verbatim round 9
// =============================================================================
__global__ __launch_bounds__(256) void k_init(const float* __restrict__ x) {
    __shared__ float sm[256 * 33];
    __shared__ float sc[32];
    __shared__ float sred[256];
    __shared__ int   sidx[256];
    __shared__ float s_S;
    __shared__ float s_bv;
    __shared__ int   s_bi;
    __shared__ int   s_idx;
    int tid = threadIdx.x;

    if (blockIdx.x == 0) {
        if (tid == 0) {
            unsigned kh = 0u, kl = 42u;   // jax.random.key(42) -> (0, 42)
            for (int i = 0; i < KC; i++) {
#if PARTITIONABLE
                unsigned a0, a1, b0, b1;
                threefry(kh, kl, 0u, 0u, a0, a1);   // new key = enc(0,0)
                threefry(kh, kl, 0u, 1u, b0, b1);   // subkey  = enc(0,1)
                g_keys[i][0] = b0; g_keys[i][1] = b1;
                kh = a0; kl = a1;
#else
                unsigned p0, q0, p1, q1;
                threefry(kh, kl, 0u, 2u, p0, q0);
                threefry(kh, kl, 1u, 3u, p1, q1);
                g_keys[i][0] = q0; g_keys[i][1] = q1;
                kh = p0; kl = p1;
#endif
            }
            unsigned lo;
#if PARTITIONABLE
            unsigned k2h, k2l, a, b;
            threefry(g_keys[0][0], g_keys[0][1], 0u, 1u, k2h, k2l);
            threefry(k2h, k2l, 0u, 0u, a, b);
            lo = a ^ b;
#else
            unsigned p0, q0, p1, q1, a, b;
            threefry(g_keys[0][0], g_keys[0][1], 0u, 2u, p0, q0);
            threefry(g_keys[0][0], g_keys[0][1], 1u, 3u, p1, q1);
            threefry(q0, q1, 0u, 0u, a, b);
            lo = a;
#endif
            s_idx = (int)(lo & (NPTS - 1));
            g_notclose = 0;
        }
        __syncthreads();
        g_cents[tid] = x[(size_t)s_idx * DIM + tid];
    }
    gbar();

    // ---- fused pass: x2 (exact fold) + distance to center 0 ------------------
    {
        float bsum = 0.f;
        for (int ch0 = blockIdx.x; ch0 < NCHUNK; ch0 += NBLK) {
            int p0 = ch0 * 256;
            float accx = 0.f, accd = 0.f;
            for (int ch = 0; ch < 8; ch++) {
                if (tid < 32) sc[tid] = g_cents[ch * 32 + tid];
#pragma unroll
                for (int l = 0; l < 32; l++) {
                    int idx = l * 256 + tid;
                    int row = idx >> 5, col = idx & 31;
                    sm[row * 33 + col] = x[(size_t)(p0 + row) * DIM + ch * 32 + col];
                }
                __syncthreads();
#pragma unroll
                for (int col = 0; col < 32; col++) {
                    float v = sm[tid * 33 + col];
                    accx = __fadd_rn(accx, __fmul_rn(v, v));
                    float d = __fsub_rn(v, sc[col]);
                    accd = __fadd_rn(accd, __fmul_rn(d, d));
                }
                __syncthreads();
            }
            g_x2[p0 + tid] = accx;
            float dc = __fsqrt_rn(fmaxf(accd, 0.f));
            g_mind[p0 + tid] = dc;
            sred[tid] = dc;
            __syncthreads();
            for (int o = 128; o; o >>= 1) {
                if (tid < o) sred[tid] += sred[tid + o];
                __syncthreads();
            }
            if (tid == 0) bsum += sred[0];
            __syncthreads();
        }
        if (tid == 0) g_sumpart[blockIdx.x] = bsum;
    }
    gbar();

    // ---- kmeans++ loop --------------------------------------------------------
    for (int i = 1; i < KC; i++) {
        if (tid == 0) {
            float S = 0.f;
            for (int b = 0; b < NBLK; b++) S += g_sumpart[b];
            s_S = S;
            s_bv = -3.4e38f; s_bi = 0x7fffffff;
        }
        __syncthreads();
        float S = s_S;
        unsigned kh = g_keys[i][0], kl = g_keys[i][1];
        for (int ch0 = blockIdx.x; ch0 < NCHUNK; ch0 += NBLK) {
            int p = ch0 * 256 + tid;
            unsigned bits;
#if PARTITIONABLE
            { unsigned a, b; threefry(kh, kl, 0u, (unsigned)p, a, b); bits = a ^ b; }
#else
            {
                unsigned a, b;
                if (p < NPTS / 2) { threefry(kh, kl, (unsigned)p, (unsigned)(p + NPTS / 2), a, b); bits = a; }
                else              { threefry(kh, kl, (unsigned)(p - NPTS / 2), (unsigned)p, a, b); bits = b; }
            }
#endif
            float f = __fsub_rn(__uint_as_float((bits >> 9) | 0x3f800000u), 1.0f);
            float u = fmaxf(__fadd_rn(f, TINYF), TINYF);
            float g = -logf(-logf(u));
            float val = __fadd_rn(logf(__fadd_rn(__fdiv_rn(g_mind[p], S), 1e-30f)), g);

            sred[tid] = val; sidx[tid] = p;
            __syncthreads();
            for (int o = 128; o; o >>= 1) {
                if (tid < o) {
                    float v2 = sred[tid + o]; int i2 = sidx[tid + o];
                    if (v2 > sred[tid] || (v2 == sred[tid] && i2 < sidx[tid])) {
                        sred[tid] = v2; sidx[tid] = i2;
                    }
                }
                __syncthreads();
            }
            if (tid == 0) {
                if (sred[0] > s_bv || (sred[0] == s_bv && sidx[0] < s_bi)) {
                    s_bv = sred[0]; s_bi = sidx[0];
                }
            }
            __syncthreads();
        }
        if (tid == 0) { g_amaxv[blockIdx.x] = s_bv; g_amaxi[blockIdx.x] = s_bi; }
        gbar();

        if (blockIdx.x == 0) {
            if (tid == 0) {
                float bv = g_amaxv[0]; int bi = g_amaxi[0];
                for (int b = 1; b < NBLK; b++) {
                    float v = g_amaxv[b]; int ii = g_amaxi[b];
                    if (v > bv || (v == bv && ii < bi)) { bv = v; bi = ii; }
                }
                s_idx = bi;
            }
            __syncthreads();
            g_cents[i * DIM + tid] = x[(size_t)s_idx * DIM + tid];
        }
        gbar();

        if (i < KC - 1) {
            float bsum = 0.f;
            for (int ch0 = blockIdx.x; ch0 < NCHUNK; ch0 += NBLK) {
                int p0 = ch0 * 256;
                float accd = 0.f;
                for (int ch = 0; ch < 8; ch++) {
                    if (tid < 32) sc[tid] = g_cents[i * DIM + ch * 32 + tid];
#pragma unroll
                    for (int l = 0; l < 32; l++) {
                        int idx = l * 256 + tid;
                        int row = idx >> 5, col = idx & 31;
                        sm[row * 33 + col] = x[(size_t)(p0 + row) * DIM + ch * 32 + col];
                    }
                    __syncthreads();
#pragma unroll
                    for (int col = 0; col < 32; col++) {
                        float d = __fsub_rn(sm[tid * 33 + col], sc[col]);
                        accd = __fadd_rn(accd, __fmul_rn(d, d));
                    }
                    __syncthreads();
                }
                float dc = __fsqrt_rn(fmaxf(accd, 0.f));
                int p = p0 + tid;
                float m = fminf(g_mind[p], dc);
                g_mind[p] = m;
                sred[tid] = m;
                __syncthreads();
                for (int o = 128; o; o >>= 1) {
                    if (tid < o) sred[tid] += sred[tid + o];
                    __syncthreads();
                }
                if (tid == 0) bsum += sred[0];
                __syncthreads();
            }
            if (tid == 0) g_sumpart[blockIdx.x] = bsum;
            gbar();
        }
    }
}

// =============================================================================
// Kernel 2: Lloyd loop — round 9 verbatim EXCEPT the prefix phase, which is
// now parallel: block c scans cluster c's 512 hist values (block scan),
// block 0 scans the 128 totals, placement adds g_base[c] on the fly.
// =============================================================================
__global__ __launch_bounds__(256) void k_lloyd(const float* __restrict__ x) {
    __shared__ float As[32 * ASTR];
    __shared__ float Bs[32 * ASTR];
    __shared__ int   sh[KC];
    __shared__ int   soffw[8][KC];
    __shared__ float smc[256];
    __shared__ int   swsum[8];
    int tid = threadIdx.x;

    // c2 init (exact sequential fold)
    if (blockIdx.x < KC) {
        smc[tid] = g_cents[blockIdx.x * DIM + tid];
        __syncthreads();
        if (tid == 0) {
            float s = 0.f;
            for (int d = 0; d < DIM; d++)
                s = __fadd_rn(s, __fmul_rn(smc[d], smc[d]));
            g_c2[blockIdx.x] = s;
        }
    }
    gbar();

    for (int it = 0; it < LLOYD_MAX; it++) {
        // ---- assign: round-9 scalar tile GEMM + quantized comparator ----
        int tx = tid & 15, ty = tid >> 4;
        for (int t = blockIdx.x; t < NTILE; t += NBLK) {
            int p0 = t * 128;
            float acc[8][8];
#pragma unroll
            for (int i = 0; i < 8; i++)
#pragma unroll
                for (int j = 0; j < 8; j++) acc[i][j] = 0.f;

            for (int k0 = 0; k0 < DIM; k0 += 32) {
#pragma unroll
                for (int l = 0; l < 4; l++) {
                    int idx = tid + 256 * l;
                    int pt = idx >> 3, j = idx & 7;
                    float4 va = *(const float4*)&x[(size_t)(p0 + pt) * DIM + k0 + j * 4];
                    As[(j * 4 + 0) * ASTR + pt] = va.x; As[(j * 4 + 1) * ASTR + pt] = va.y;
                    As[(j * 4 + 2) * ASTR + pt] = va.z; As[(j * 4 + 3) * ASTR + pt] = va.w;
                    float4 vb = *(const float4*)&g_cents[pt * DIM + k0 + j * 4];
                    Bs[(j * 4 + 0) * ASTR + pt] = vb.x; Bs[(j * 4 + 1) * ASTR + pt] = vb.y;
                    Bs[(j * 4 + 2) * ASTR + pt] = vb.z; Bs[(j * 4 + 3) * ASTR + pt] = vb.w;
                }
                __syncthreads();
#pragma unroll
                for (int kk = 0; kk < 32; kk++) {
                    float4 a0 = *(float4*)&As[kk * ASTR + ty * 8];
                    float4 a1 = *(float4*)&As[kk * ASTR + ty * 8 + 4];
                    float4 b0 = *(float4*)&Bs[kk * ASTR + tx * 8];
                    float4 b1 = *(float4*)&Bs[kk * ASTR + tx * 8 + 4];
                    float a[8] = {a0.x, a0.y, a0.z, a0.w, a1.x, a1.y, a1.z, a1.w};
                    float bb[8] = {b0.x, b0.y, b0.z, b0.w, b1.x, b1.y, b1.z, b1.w};
#pragma unroll
                    for (int i = 0; i < 8; i++)
#pragma unroll
                        for (int j = 0; j < 8; j++)
                            acc[i][j] = fmaf(a[i], bb[j], acc[i][j]);
                }
                __syncthreads();
            }
            // ref comparator: d = sqrt(max((x2+c2) - 2*dot, 0)); argmin, first index
#pragma unroll
            for (int i = 0; i < 8; i++) {
                float x2p = g_x2[p0 + ty * 8 + i];
                float bv = 3.4e38f; int bc = 0;
#pragma unroll
                for (int j = 0; j < 8; j++) {
                    int c = tx * 8 + j;
                    float d2 = __fsub_rn(__fadd_rn(x2p, g_c2[c]), __fmul_rn(2.0f, acc[i][j]));
                    float d = __fsqrt_rn(fmaxf(d2, 0.0f));
                    if (d < bv) { bv = d; bc = c; }
                }
#pragma unroll
                for (int o = 8; o; o >>= 1) {
                    float ov = __shfl_xor_sync(0xffffffffu, bv, o, 16);
                    int   oc = __shfl_xor_sync(0xffffffffu, bc, o, 16);
                    if (ov < bv || (ov == bv && oc < bc)) { bv = ov; bc = oc; }
                }
                if (tx == 0) g_ids[p0 + ty * 8 + i] = bc;
            }
        }
        gbar();

        if (blockIdx.x == 0 && tid == 0) g_notclose = 0;

        // ---- per-chunk histograms (round 9) ----
        for (int b = blockIdx.x; b < NCHUNK; b += NBLK) {
            if (tid < KC) sh[tid] = 0;
            __syncthreads();
            atomicAdd(&sh[g_ids[b * 256 + tid]], 1);
            __syncthreads();
            if (tid < KC) g_hist[b * KC + tid] = sh[tid];
            __syncthreads();
        }
        gbar();

        // ---- PARALLEL prefix: block c scans cluster c's NCHUNK values ----
        if (blockIdx.x < KC) {
            int c = blockIdx.x;
            int h0 = g_hist[(2 * tid) * KC + c];
            int h1 = g_hist[(2 * tid + 1) * KC + c];
            int s = h0 + h1;
            int lane = tid & 31, w = tid >> 5;
            int v = s;
#pragma unroll
            for (int o = 1; o < 32; o <<= 1) {
                int n = __shfl_up_sync(0xffffffffu, v, o);
                if (lane >= o) v += n;
            }
            if (lane == 31) swsum[w] = v;
            __syncthreads();
            if (tid < 8) {
                int tsum = swsum[tid];
#pragma unroll
                for (int o = 1; o < 8; o <<= 1) {
                    int n = __shfl_up_sync(0xffu, tsum, o);
                    if (tid >= o) tsum += n;
                }
                swsum[tid] = tsum;   // inclusive warp totals
            }
            __syncthreads();
            int wbase = (w == 0) ? 0 : swsum[w - 1];
            int excl = wbase + v - s;        // exclusive prefix of this pair
            g_off[(2 * tid) * KC + c] = excl;
            g_off[(2 * tid + 1) * KC + c] = excl + h0;
            if (tid == 255) g_tot[c] = wbase + v;
        }
        gbar();

        // ---- tiny serial scan of 128 cluster totals (block 0) ----
        if (blockIdx.x == 0 && tid == 0) {
            int base = 0;
            for (int k = 0; k < KC; k++) { g_base[k] = base; base += g_tot[k]; }
        }
        gbar();

        // ---- stable placement (one warp per 256-pt chunk; base added here) ----
        {
            int w = tid >> 5, lane = tid & 31;
            for (int b = blockIdx.x * 8 + w; b < NCHUNK; b += NBLK * 8) {
                for (int l = lane; l < KC; l += 32)
                    soffw[w][l] = g_off[b * KC + l] + g_base[l];
                __syncwarp();
                if (lane == 0) {
                    for (int q = 0; q < 256; q++) {
                        int p = b * 256 + q;
                        int c = g_ids[p];
                        g_order[soffw[w][c]++] = p;
                    }
                }
                __syncwarp();
            }
        }
        gbar();

        // ---- segment mean: exact ascending-p fold, 8-way (round 9) ----
        if (blockIdx.x < KC) {
            int c = blockIdx.x;
            int j0 = g_base[c], cnt = g_tot[c];
            float acc = 0.f;
            int full = cnt & ~7;
            for (int j = 0; j < full; j += 8) {
                int pp[8];
#pragma unroll
                for (int q = 0; q < 8; q++) pp[q] = g_order[j0 + j + q];
                float vv[8];
#pragma unroll
                for (int q = 0; q < 8; q++) vv[q] = x[(size_t)pp[q] * DIM + tid];
#pragma unroll
                for (int q = 0; q < 8; q++) acc = __fadd_rn(acc, vv[q]);
            }
            for (int j = full; j < cnt; j++)
                acc = __fadd_rn(acc, x[(size_t)g_order[j0 + j] * DIM + tid]);

            float nv = __fdiv_rn(acc, fmaxf((float)cnt, 1.0f));
            g_newc[c * DIM + tid] = nv;
            float ov = g_cents[c * DIM + tid];
            float thr = __fadd_rn(1e-8f, __fmul_rn(1e-4f, fabsf(nv)));
            int fail = fabsf(__fsub_rn(ov, nv)) > thr;
            if (__syncthreads_or(fail)) { if (tid == 0) atomicOr(&g_notclose, 1); }
        }
        gbar();

        // ---- commit or break ----
        int done = (*(volatile int*)&g_notclose) == 0;
        if (!done && blockIdx.x < KC) {
            float v = g_newc[blockIdx.x * DIM + tid];
            g_cents[blockIdx.x * DIM + tid] = v;
            smc[tid] = v;
            __syncthreads();
            if (tid == 0) {
                float s = 0.f;
                for (int d = 0; d < DIM; d++)
                    s = __fadd_rn(s, __fmul_rn(smc[d], smc[d]));
                g_c2[blockIdx.x] = s;
            }
        }
        gbar();
        if (done) break;
    }
}

// =============================================================================
// Kernel 3: loss GEMM + fused log-softmax (verbatim round 9)
// =============================================================================
__global__ __launch_bounds__(256, 2) void k_loss(const float* __restrict__ x) {
    __shared__ float As[32 * ASTR];
    __shared__ float Bs[32 * ASTR];
    __shared__ float sl[16];
    int tid = threadIdx.x;
    int tx = tid & 15, ty = tid >> 4;
    int p0 = blockIdx.x * 128;
    float acc[8][8];
#pragma unroll
    for (int i = 0; i < 8; i++)
#pragma unroll
        for (int j = 0; j < 8; j++) acc[i][j] = 0.f;

    for (int k0 = 0; k0 < DIM; k0 += 32) {
#pragma unroll
        for (int l = 0; l < 4; l++) {
            int idx = tid + 256 * l;
            int pt = idx >> 3, j = idx & 7;
            float4 va = *(const float4*)&x[(size_t)(p0 + pt) * DIM + k0 + j * 4];
            As[(j * 4 + 0) * ASTR + pt] = va.x; As[(j * 4 + 1) * ASTR + pt] = va.y;
            As[(j * 4 + 2) * ASTR + pt] = va.z; As[(j * 4 + 3) * ASTR + pt] = va.w;
            float4 vb = *(const float4*)&g_cents[pt * DIM + k0 + j * 4];
            Bs[(j * 4 + 0) * ASTR + pt] = vb.x; Bs[(j * 4 + 1) * ASTR + pt] = vb.y;
            Bs[(j * 4 + 2) * ASTR + pt] = vb.z; Bs[(j * 4 + 3) * ASTR + pt] = vb.w;
        }
        __syncthreads();
#pragma unroll
        for (int kk = 0; kk < 32; kk++) {
            float4 a0 = *(float4*)&As[kk * ASTR + ty * 8];
            float4 a1 = *(float4*)&As[kk * ASTR + ty * 8 + 4];
            float4 b0 = *(float4*)&Bs[kk * ASTR + tx * 8];
            float4 b1 = *(float4*)&Bs[kk * ASTR + tx * 8 + 4];
            float a[8] = {a0.x, a0.y, a0.z, a0.w, a1.x, a1.y, a1.z, a1.w};
            float bb[8] = {b0.x, b0.y, b0.z, b0.w, b1.x, b1.y, b1.z, b1.w};
#pragma unroll
            for (int i = 0; i < 8; i++)
#pragma unroll
                for (int j = 0; j < 8; j++)
                    acc[i][j] = fmaf(a[i], bb[j], acc[i][j]);
        }
        __syncthreads();
    }

    float lsum = 0.f;
#pragma unroll
    for (int i = 0; i < 8; i++) {
        int p = p0 + ty * 8 + i;
        int id = g_ids[p];
        float z[8];
        float zm = -3.4e38f;
#pragma unroll
        for (int j = 0; j < 8; j++) {
            z[j] = __fdiv_rn(acc[i][j], 0.1f);
            zm = fmaxf(zm, z[j]);
        }
#pragma unroll
        for (int o = 8; o; o >>= 1) zm = fmaxf(zm, __shfl_xor_sync(0xffffffffu, zm, o, 16));
        float se = 0.f, zid = 0.f;
#pragma unroll
        for (int j = 0; j < 8; j++) {
            se += expf(__fsub_rn(z[j], zm));
            if (tx * 8 + j == id) zid = z[j];
        }
#pragma unroll
        for (int o = 8; o; o >>= 1) {
            se += __shfl_xor_sync(0xffffffffu, se, o, 16);
            zid += __shfl_xor_sync(0xffffffffu, zid, o, 16);
        }
        if (tx == 0) lsum += (zm + logf(se)) - zid;
    }
    if (tx == 0) sl[ty] = lsum;
    __syncthreads();
    if (tid == 0) {
        float t = 0.f;
#pragma unroll
        for (int w = 0; w < 16; w++) t += sl[w];
        g_losspart[blockIdx.x] = t;
    }
}

__global__ void k_loss_final(float* __restrict__ out) {
    __shared__ float sr[256];
    int t = threadIdx.x;
    float s = g_losspart[t] + g_losspart[t + 256] +
              g_losspart[t + 512] + g_losspart[t + 768];
    sr[t] = s;
    __syncthreads();
    for (int o = 128; o; o >>= 1) { if (t < o) sr[t] += sr[t + o]; __syncthreads(); }
    if (t == 0) out[0] = __fdiv_rn(sr[0], (float)NPTS);
}

// ---- launch: 4 graph nodes total --------------------------------------------
extern "C" void kernel_launch(void* const* d_in, const int* in_sizes, int n_in,
                              void* d_out, int out_size) {
    const float* x = (const float*)d_in[0];
    float* out = (float*)d_out;
    (void)in_sizes; (void)n_in; (void)out_size;

    k_init<<<NBLK, 256>>>(x);
    k_lloyd<<<NBLK, 256>>>(x);
    k_loss<<<NTILE, 256>>>(x);
    k_loss_final<<<1, 256>>>(out);
}